// round 6
// baseline (speedup 1.0000x reference)
#include <cuda_runtime.h>
#include <cuda_bf16.h>
#include <cstdint>

// ============================================================================
// VanillaRNNSequenceModel: B=4, T=1024, D=256, VOCAB=32000, 2 layers
//   x = embed[ids]                                  (B,T,D)
//   h0 = tanh([x_t, h0] @ W0^T + b0)                per step
//   h1 = tanh([h0, h1] @ W1^T + b1)                 per step  (rnn_out = h1)
//   logits = rnn_out @ head_w^T                     (B,T,V)
// Outputs: logits (B*T*V floats) ++ final_hidden (2*B*D floats)
// ============================================================================

typedef unsigned long long u64;

#define BATCH   4
#define T_STEPS 1024
#define DDIM    256
#define VDIM    32000
#define CL      8          // CTAs per cluster (one cluster per batch element)

// scratch for rnn_out (B,T,D) fp32 = 4 MB (static device array: no allocations)
__device__ float g_rnn[BATCH * T_STEPS * DDIM];

// ---------------- packed f32x2 helpers (Blackwell FFMA2) -------------------
__device__ __forceinline__ u64 fma2(u64 a, u64 b, u64 c) {
    u64 d;
    asm("fma.rn.f32x2 %0, %1, %2, %3;" : "=l"(d) : "l"(a), "l"(b), "l"(c));
    return d;
}
__device__ __forceinline__ u64 pack2(float lo, float hi) {
    u64 d;
    asm("mov.b64 %0, {%1, %2};" : "=l"(d) : "f"(lo), "f"(hi));
    return d;
}
__device__ __forceinline__ float lo32(u64 v) { return __uint_as_float((unsigned)(v & 0xffffffffull)); }
__device__ __forceinline__ float hi32(u64 v) { return __uint_as_float((unsigned)(v >> 32)); }

// ============================================================================
// Scan kernel: 4 clusters x 8 CTAs x 256 threads. Cluster c handles batch c.
// Thread (rank, tid): tg = rank*256+tid; o = tg>>3 (output row), p = tg&7
// (64-element k-slice of the 512-long concat dot product).
// Weights held in registers for all 1024 steps. h vectors ping-pong in SMEM,
// replicated per-CTA, updated cross-CTA via st.shared::cluster + cluster barrier.
// ============================================================================
__global__ void __launch_bounds__(256, 1) __cluster_dims__(CL, 1, 1)
rnn_scan_kernel(const int*   __restrict__ ids,
                const float* __restrict__ embed,
                const float* __restrict__ W0,
                const float* __restrict__ b0,
                const float* __restrict__ W1,
                const float* __restrict__ b1,
                float*       __restrict__ fh)   // final_hidden (2,B,D)
{
    __shared__ __align__(16) float xs [2][DDIM];
    __shared__ __align__(16) float h0s[2][DDIM];
    __shared__ __align__(16) float h1s[2][DDIM];

    unsigned rank;
    asm("mov.u32 %0, %%cluster_ctarank;" : "=r"(rank));
    const int tid   = threadIdx.x;
    const int batch = blockIdx.x / CL;
    const int tg    = (int)rank * 256 + tid;
    const int o     = tg >> 3;     // 0..255 output index
    const int p     = tg & 7;      // 0..7 k-slice

    // --- load persistent weight slices into registers (64 floats = 32 f32x2 each layer)
    u64 w0r[32], w1r[32];
    {
        const u64* g0 = reinterpret_cast<const u64*>(W0 + (size_t)o * 512 + p * 64);
        const u64* g1 = reinterpret_cast<const u64*>(W1 + (size_t)o * 512 + p * 64);
        #pragma unroll
        for (int j = 0; j < 32; j++) { w0r[j] = g0[j]; w1r[j] = g1[j]; }
    }
    const float bias0 = __ldg(b0 + o);
    const float bias1 = __ldg(b1 + o);

    // --- init state + first x
    h0s[0][tid] = 0.0f;
    h1s[0][tid] = 0.0f;
    if (tid < 64) {
        int id0 = __ldg(ids + batch * T_STEPS);
        reinterpret_cast<float4*>(xs[0])[tid] =
            __ldg(reinterpret_cast<const float4*>(embed + (size_t)id0 * DDIM) + tid);
    }
    __syncthreads();

    const unsigned h0base = (unsigned)__cvta_generic_to_shared(&h0s[0][0]);
    const unsigned h1base = (unsigned)__cvta_generic_to_shared(&h1s[0][0]);

    for (int t = 0; t < T_STEPS; ++t) {
        const int par = t & 1;
        const int nxt = par ^ 1;

        // prefetch x_{t+1} (consumed next step; stored to SMEM before end-of-step barrier)
        float4 xnext = make_float4(0.f, 0.f, 0.f, 0.f);
        const bool pf = (tid < 64) && (t + 1 < T_STEPS);
        if (pf) {
            int idn = __ldg(ids + batch * T_STEPS + t + 1);
            xnext = __ldg(reinterpret_cast<const float4*>(embed + (size_t)idn * DDIM) + tid);
        }

        // ------------------ layer 0: h0_new = tanh([x_t, h0] @ W0^T + b0)
        {
            const float* in  = (p < 4) ? &xs[par][p * 64] : &h0s[par][(p - 4) * 64];
            const u64*   in2 = reinterpret_cast<const u64*>(in);
            u64 a0 = 0, a1 = 0, a2 = 0, a3 = 0;
            #pragma unroll
            for (int j = 0; j < 32; j += 4) {
                a0 = fma2(w0r[j + 0], in2[j + 0], a0);
                a1 = fma2(w0r[j + 1], in2[j + 1], a1);
                a2 = fma2(w0r[j + 2], in2[j + 2], a2);
                a3 = fma2(w0r[j + 3], in2[j + 3], a3);
            }
            float s = lo32(a0) + hi32(a0) + lo32(a1) + hi32(a1)
                    + lo32(a2) + hi32(a2) + lo32(a3) + hi32(a3);
            // reduce across the 8 p-slices (lanes (o&3)*8 + p within the warp)
            s += __shfl_xor_sync(0xffffffffu, s, 1);
            s += __shfl_xor_sync(0xffffffffu, s, 2);
            s += __shfl_xor_sync(0xffffffffu, s, 4);
            if (p == 0) {
                float v = tanhf(s + bias0);
                unsigned addr = h0base + (unsigned)((nxt * DDIM + o) * 4);
                #pragma unroll
                for (int r = 0; r < CL; r++) {
                    asm volatile(
                        "{ .reg .b32 ra; mapa.shared::cluster.u32 ra, %0, %1; "
                        "st.shared::cluster.f32 [ra], %2; }"
                        :: "r"(addr), "r"(r), "f"(v) : "memory");
                }
            }
        }
        asm volatile("barrier.cluster.arrive.aligned;\n\t"
                     "barrier.cluster.wait.aligned;" ::: "memory");

        // ------------------ layer 1: h1_new = tanh([h0_new, h1] @ W1^T + b1)
        {
            const float* in  = (p < 4) ? &h0s[nxt][p * 64] : &h1s[par][(p - 4) * 64];
            const u64*   in2 = reinterpret_cast<const u64*>(in);
            u64 a0 = 0, a1 = 0, a2 = 0, a3 = 0;
            #pragma unroll
            for (int j = 0; j < 32; j += 4) {
                a0 = fma2(w1r[j + 0], in2[j + 0], a0);
                a1 = fma2(w1r[j + 1], in2[j + 1], a1);
                a2 = fma2(w1r[j + 2], in2[j + 2], a2);
                a3 = fma2(w1r[j + 3], in2[j + 3], a3);
            }
            float s = lo32(a0) + hi32(a0) + lo32(a1) + hi32(a1)
                    + lo32(a2) + hi32(a2) + lo32(a3) + hi32(a3);
            s += __shfl_xor_sync(0xffffffffu, s, 1);
            s += __shfl_xor_sync(0xffffffffu, s, 2);
            s += __shfl_xor_sync(0xffffffffu, s, 4);
            if (p == 0) {
                float v = tanhf(s + bias1);
                unsigned addr = h1base + (unsigned)((nxt * DDIM + o) * 4);
                #pragma unroll
                for (int r = 0; r < CL; r++) {
                    asm volatile(
                        "{ .reg .b32 ra; mapa.shared::cluster.u32 ra, %0, %1; "
                        "st.shared::cluster.f32 [ra], %2; }"
                        :: "r"(addr), "r"(r), "f"(v) : "memory");
                }
                g_rnn[((size_t)batch * T_STEPS + t) * DDIM + o] = v;
            }
        }
        // commit prefetched x_{t+1} to local SMEM (other buffer; no reader until next step)
        if (pf) reinterpret_cast<float4*>(xs[nxt])[tid] = xnext;

        asm volatile("barrier.cluster.arrive.aligned;\n\t"
                     "barrier.cluster.wait.aligned;" ::: "memory");
    }

    // T=1024 is even -> final state lives in parity-0 buffers
    if (rank == 0) {
        fh[0 * BATCH * DDIM + batch * DDIM + tid] = h0s[0][tid];
        fh[1 * BATCH * DDIM + batch * DDIM + tid] = h1s[0][tid];
    }
}

// ============================================================================
// Head GEMM: C[4096, 32000] = rnn_out[4096,256] @ head_w[32000,256]^T, fp32.
// 128x128 block tile, 8x8 per thread, BK=32 (8 k-tiles), all accumulation via
// packed fma.rn.f32x2 (2 FMA/instr -> 128 FMA/cyc/SM vs 64 for 3-reg FFMA).
// ============================================================================
__global__ void __launch_bounds__(256, 2)
head_gemm_kernel(const float* __restrict__ W,   // head_w [32000,256]
                 float*       __restrict__ C)   // logits [4096,32000]
{
    __shared__ __align__(16) float As[32][128];
    __shared__ __align__(16) float Bs[32][128];

    const int tid = threadIdx.x;
    const int n0  = blockIdx.x * 128;
    const int m0  = blockIdx.y * 128;
    const int tx  = tid & 15;      // n-tile 0..15
    const int ty  = tid >> 4;      // m-tile 0..15
    const int lr  = tid >> 3;      // load row 0..31
    const int lc  = tid & 7;       // load float4-col 0..7

    u64 acc[32];
    #pragma unroll
    for (int i = 0; i < 32; i++) acc[i] = 0ull;

    const float* A = g_rnn;

    for (int ko = 0; ko < 8; ++ko) {
        #pragma unroll
        for (int i = 0; i < 4; ++i) {
            int r = lr + i * 32;
            float4 va = __ldg(reinterpret_cast<const float4*>(A + (size_t)(m0 + r) * DDIM) + ko * 8 + lc);
            float4 vb = __ldg(reinterpret_cast<const float4*>(W + (size_t)(n0 + r) * DDIM) + ko * 8 + lc);
            As[lc * 4 + 0][r] = va.x; As[lc * 4 + 1][r] = va.y;
            As[lc * 4 + 2][r] = va.z; As[lc * 4 + 3][r] = va.w;
            Bs[lc * 4 + 0][r] = vb.x; Bs[lc * 4 + 1][r] = vb.y;
            Bs[lc * 4 + 2][r] = vb.z; Bs[lc * 4 + 3][r] = vb.w;
        }
        __syncthreads();

        #pragma unroll
        for (int k = 0; k < 32; ++k) {
            float4 a01 = reinterpret_cast<const float4*>(As[k])[ty * 2 + 0];
            float4 a23 = reinterpret_cast<const float4*>(As[k])[ty * 2 + 1];
            float4 b01 = reinterpret_cast<const float4*>(Bs[k])[tx * 2 + 0];
            float4 b23 = reinterpret_cast<const float4*>(Bs[k])[tx * 2 + 1];
            u64 b2[4];
            b2[0] = pack2(b01.x, b01.y); b2[1] = pack2(b01.z, b01.w);
            b2[2] = pack2(b23.x, b23.y); b2[3] = pack2(b23.z, b23.w);
            float am[8] = {a01.x, a01.y, a01.z, a01.w, a23.x, a23.y, a23.z, a23.w};
            #pragma unroll
            for (int mi = 0; mi < 8; ++mi) {
                u64 ad = pack2(am[mi], am[mi]);
                #pragma unroll
                for (int nj = 0; nj < 4; ++nj)
                    acc[mi * 4 + nj] = fma2(ad, b2[nj], acc[mi * 4 + nj]);
            }
        }
        __syncthreads();
    }

    // epilogue: 8 rows x 8 cols per thread, two float4 stores per row
    #pragma unroll
    for (int mi = 0; mi < 8; ++mi) {
        size_t row = (size_t)m0 + ty * 8 + mi;
        float4 c0 = make_float4(lo32(acc[mi * 4 + 0]), hi32(acc[mi * 4 + 0]),
                                lo32(acc[mi * 4 + 1]), hi32(acc[mi * 4 + 1]));
        float4 c1 = make_float4(lo32(acc[mi * 4 + 2]), hi32(acc[mi * 4 + 2]),
                                lo32(acc[mi * 4 + 3]), hi32(acc[mi * 4 + 3]));
        float4* dst = reinterpret_cast<float4*>(C + row * VDIM + n0 + tx * 8);
        dst[0] = c0;
        dst[1] = c1;
    }
}

// ============================================================================
// kernel_launch
// metadata order: input_ids(i32), embed(f32), W0, b0, W1, b1, head_w ; out f32
// d_out layout: logits (B*T*V) followed by final_hidden (2*B*D)
// ============================================================================
extern "C" void kernel_launch(void* const* d_in, const int* in_sizes, int n_in,
                              void* d_out, int out_size) {
    (void)in_sizes; (void)n_in;
    const int*   ids    = (const int*)  d_in[0];
    const float* embed  = (const float*)d_in[1];
    const float* W0     = (const float*)d_in[2];
    const float* b0     = (const float*)d_in[3];
    const float* W1     = (const float*)d_in[4];
    const float* b1     = (const float*)d_in[5];
    const float* head_w = (const float*)d_in[6];

    float* out = (float*)d_out;
    float* fh  = out + ((size_t)out_size - 2 * BATCH * DDIM);

    // recurrent scan (4 clusters of 8 CTAs; __cluster_dims__ is compile-time)
    rnn_scan_kernel<<<BATCH * CL, 256>>>(ids, embed, W0, b0, W1, b1, fh);

    // head projection
    dim3 grid(VDIM / 128, (BATCH * T_STEPS) / 128);
    head_gemm_kernel<<<grid, 256>>>(head_w, out);
}